// round 16
// baseline (speedup 1.0000x reference)
#include <cuda_runtime.h>
#include <cuda_bf16.h>
#include <mma.h>
#include <math.h>

using namespace nvcuda;

// Problem constants
#define BS   8
#define NQ   4096
#define E    256
#define NH   8
#define NP   4
#define HD   32
#define HH   64
#define WW   64
#define M_TOT (BS*NQ)      // 32768
#define N1   352

// GEMM tiling
#define BM   128
#define BN   128
#define BK   32
#define LDAH 40                    // bf16 leading dim (80B rows)
#define LDC  136                   // float C staging leading dim
#define NKT  (E/BK)                // 8
#define STAGE ((BM+BN)*LDAH)       // 10240 bf16 per stage
#define DYN_SMEM 69632             // max(2*STAGE*2 = 40960, BM*LDC*4 = 69632)

// Scratch
__device__ __nv_bfloat16 g_val [BS*NH*NQ*HD + 4096];  // [b,h,pos,d] + guard pad
__device__ float         g_off [M_TOT*64];
__device__ float         g_attn[M_TOT*32];
__device__ __nv_bfloat16 g_samp[M_TOT*E];
__device__ __nv_bfloat16 g_w1  [N1*E];
__device__ __nv_bfloat16 g_w2  [E*E];
__device__ float         g_b1  [N1];
__device__ float4        g_sw  [M_TOT*NH*NP];         // premult corner weights
__device__ int           g_sidx[M_TOT*NH*NP];         // clamped base index

// ---------------------------------------------------------------------------
__device__ __forceinline__ void cp_async16(void* sdst, const void* gsrc) {
    unsigned s = (unsigned)__cvta_generic_to_shared(sdst);
    asm volatile("cp.async.cg.shared.global [%0], [%1], 16;\n" :: "r"(s), "l"(gsrc));
}

// ---------------------------------------------------------------------------
// Prep: weights -> bf16 (concat) + biases only (query handled in gemm1)
// ---------------------------------------------------------------------------
__global__ __launch_bounds__(256) void prep_w(
        const float* __restrict__ vw, const float* __restrict__ vb,
        const float* __restrict__ ow, const float* __restrict__ ob,
        const float* __restrict__ aw, const float* __restrict__ ab,
        const float* __restrict__ outw) {
    int i = blockIdx.x * 256 + threadIdx.x;
    if (i < 256*256)      g_w1[i] = __float2bfloat16(vw[i]);
    else if (i < 320*256) g_w1[i] = __float2bfloat16(ow[i - 256*256]);
    else if (i < 352*256) g_w1[i] = __float2bfloat16(aw[i - 320*256]);
    if (i < 256*256)      g_w2[i] = __float2bfloat16(outw[i]);
    if (i < 256)          g_b1[i] = vb[i];
    else if (i < 320)     g_b1[i] = ob[i - 256];
    else if (i < 352)     g_b1[i] = ab[i - 320];
}

// ---------------------------------------------------------------------------
// bf16 cp.async pipelined mainloop. A source either bf16 (cp.async) or fp32
// (register-staged + converted). C staged to smem (fp32).
// ---------------------------------------------------------------------------
template<bool A_FP32>
__device__ __forceinline__ void bf16_mainloop(
    const void* __restrict__ Aptr, const __nv_bfloat16* __restrict__ B,
    int b_rows, int m0, int n0, unsigned char* smem_raw)
{
    __nv_bfloat16* buf = (__nv_bfloat16*)smem_raw;
    const int tid  = threadIdx.x;
    const int warp = tid >> 5;
    const int wr   = warp >> 2;    // 0..1 -> 64-row block
    const int wc   = warp & 3;     // 0..3 -> 32-col block

    wmma::fragment<wmma::accumulator, 16, 16, 16, float> c[4][2];
    #pragma unroll
    for (int i = 0; i < 4; i++)
        #pragma unroll
        for (int j = 0; j < 2; j++) wmma::fill_fragment(c[i][j], 0.0f);

    float a_regs[2][8];            // fp32 staging (A_FP32 path)

    // Load A chunk coords: it=0,1 -> rows 0..127 (A); it=2,3 -> rows 128..255 (B)
    auto issue = [&](int s, int k0) {
        __nv_bfloat16* St = buf + s * STAGE;
        if (A_FP32) {
            const float* A = (const float*)Aptr;
            #pragma unroll
            for (int it = 0; it < 2; it++) {
                int idx = tid + it * 256;
                int row = idx >> 2, cg = idx & 3;
                const float* src = A + (size_t)(m0 + row) * E + k0 + cg * 8;
                *(float4*)&a_regs[it][0] = *(const float4*)src;
                *(float4*)&a_regs[it][4] = *(const float4*)(src + 4);
            }
        } else {
            const __nv_bfloat16* A = (const __nv_bfloat16*)Aptr;
            #pragma unroll
            for (int it = 0; it < 2; it++) {
                int idx = tid + it * 256;
                int row = idx >> 2, cg = idx & 3;
                cp_async16(St + row * LDAH + cg * 8,
                           A + (size_t)(m0 + row) * E + k0 + cg * 8);
            }
        }
        #pragma unroll
        for (int it = 2; it < 4; it++) {
            int idx = tid + it * 256;
            int row = idx >> 2, cg = idx & 3;
            int gn = n0 + row - BM;
            if (gn >= b_rows) gn = b_rows - 1;
            cp_async16(St + row * LDAH + cg * 8,
                       B + (size_t)gn * E + k0 + cg * 8);
        }
        asm volatile("cp.async.commit_group;\n" ::);
    };

    auto store_a = [&](int s) {
        if (!A_FP32) return;
        __nv_bfloat16* St = buf + s * STAGE;
        #pragma unroll
        for (int it = 0; it < 2; it++) {
            int idx = tid + it * 256;
            int row = idx >> 2, cg = idx & 3;
            __nv_bfloat16 t[8];
            #pragma unroll
            for (int j = 0; j < 8; j++) t[j] = __float2bfloat16(a_regs[it][j]);
            *(uint4*)&St[row * LDAH + cg * 8] = *(uint4*)t;
        }
    };

    auto compute = [&](int s) {
        __nv_bfloat16* As = buf + s * STAGE;
        __nv_bfloat16* Bs = As + BM * LDAH;
        #pragma unroll
        for (int kk = 0; kk < BK; kk += 16) {
            wmma::fragment<wmma::matrix_a, 16, 16, 16, __nv_bfloat16, wmma::row_major> a[4];
            wmma::fragment<wmma::matrix_b, 16, 16, 16, __nv_bfloat16, wmma::col_major> b[2];
            #pragma unroll
            for (int i = 0; i < 4; i++)
                wmma::load_matrix_sync(a[i], &As[(wr * 64 + i * 16) * LDAH + kk], LDAH);
            #pragma unroll
            for (int j = 0; j < 2; j++)
                wmma::load_matrix_sync(b[j], &Bs[(wc * 32 + j * 16) * LDAH + kk], LDAH);
            #pragma unroll
            for (int i = 0; i < 4; i++)
                #pragma unroll
                for (int j = 0; j < 2; j++)
                    wmma::mma_sync(c[i][j], a[i], b[j], c[i][j]);
        }
    };

    issue(0, 0);
    store_a(0);
    for (int kt = 0; kt < NKT; kt++) {
        if (kt + 1 < NKT) {
            issue((kt + 1) & 1, (kt + 1) * BK);
            asm volatile("cp.async.wait_group 1;\n" ::);
        } else {
            asm volatile("cp.async.wait_group 0;\n" ::);
        }
        if (kt + 1 < NKT) store_a((kt + 1) & 1);  // write other buffer; safe pre-sync? no:
        __syncthreads();                           // orders A stores + B arrivals for tile kt
        compute(kt & 1);
        __syncthreads();
    }

    float* Cs = (float*)smem_raw;
    #pragma unroll
    for (int i = 0; i < 4; i++)
        #pragma unroll
        for (int j = 0; j < 2; j++)
            wmma::store_matrix_sync(&Cs[(wr * 64 + i * 16) * LDC + wc * 32 + j * 16],
                                    c[i][j], LDC, wmma::mem_row_major);
    __syncthreads();
}

// ---------------------------------------------------------------------------
// GEMM1: query(fp32, converted in-flight) @ g_w1^T (+bias)
//        -> scatter {g_val bf16, g_off, g_attn}
// ---------------------------------------------------------------------------
__global__ __launch_bounds__(256) void gemm1_tc(const float* __restrict__ query) {
    extern __shared__ unsigned char smem_raw[];
    const int m0 = blockIdx.x * BM;
    const int n0 = blockIdx.y * BN;
    const int tid = threadIdx.x;

    bf16_mainloop<true>(query, g_w1, N1, m0, n0, smem_raw);
    float* Cs = (float*)smem_raw;

    #pragma unroll
    for (int it = 0; it < 16; it++) {
        int idx = tid + it * 256;
        int mm = idx >> 5, n4 = idx & 31;
        int c = n0 + n4 * 4;
        if (c >= N1) continue;
        int m = m0 + mm;
        int b = m >> 12, q = m & 4095;
        float4 v = *(float4*)&Cs[mm * LDC + n4 * 4];
        v.x += g_b1[c];     v.y += g_b1[c + 1];
        v.z += g_b1[c + 2]; v.w += g_b1[c + 3];
        if (c < 256) {
            int h = c >> 5, d = c & 31;
            __nv_bfloat16 t[4] = {__float2bfloat16(v.x), __float2bfloat16(v.y),
                                  __float2bfloat16(v.z), __float2bfloat16(v.w)};
            *(uint2*)&g_val[((((size_t)b << 3) + h) * NQ + q) * HD + d] = *(uint2*)t;
        } else if (c < 320) {
            *(float4*)&g_off[(size_t)m * 64 + (c - 256)] = v;
        } else {
            *(float4*)&g_attn[(size_t)m * 32 + (c - 320)] = v;
        }
    }
}

// ---------------------------------------------------------------------------
// GEMM2: g_samp(bf16) @ g_w2^T + out_b + 2*query -> out
// ---------------------------------------------------------------------------
__global__ __launch_bounds__(256) void gemm2_tc(const float* __restrict__ bias,
                                                const float* __restrict__ query,
                                                float* __restrict__ out) {
    extern __shared__ unsigned char smem_raw[];
    const int m0 = blockIdx.x * BM;
    const int n0 = blockIdx.y * BN;
    const int tid = threadIdx.x;

    bf16_mainloop<false>(g_samp, g_w2, E, m0, n0, smem_raw);
    float* Cs = (float*)smem_raw;

    #pragma unroll
    for (int it = 0; it < 16; it++) {
        int idx = tid + it * 256;
        int mm = idx >> 5, n4 = idx & 31;
        int c = n0 + n4 * 4;
        size_t go = (size_t)(m0 + mm) * E + c;
        float4 v = *(float4*)&Cs[mm * LDC + n4 * 4];
        float4 bi = *(const float4*)&bias[c];
        float4 qv = *(const float4*)&query[go];
        v.x += bi.x + 2.0f * qv.x;
        v.y += bi.y + 2.0f * qv.y;
        v.z += bi.z + 2.0f * qv.z;
        v.w += bi.w + 2.0f * qv.w;
        *(float4*)&out[go] = v;
    }
}

// ---------------------------------------------------------------------------
// Sample setup: one thread per (m,h,p). Softmax-premultiplied, validity-masked
// corner weights + clamped base index (low-side clamp folds weight into base).
// ---------------------------------------------------------------------------
__global__ __launch_bounds__(256) void sample_setup() {
    const int t  = blockIdx.x * 256 + threadIdx.x;
    const int p  = t & 3;
    const int mh = t >> 2;          // m*8 + h
    const int m  = mh >> 3;
    const int q  = m & 4095;

    const float4 at = *(const float4*)&g_attn[(size_t)mh * 4];
    float mx = fmaxf(fmaxf(at.x, at.y), fmaxf(at.z, at.w));
    float e0 = __expf(at.x - mx), e1 = __expf(at.y - mx),
          e2 = __expf(at.z - mx), e3 = __expf(at.w - mx);
    float inv = 1.f / (e0 + e1 + e2 + e3);
    float awp = (p == 0 ? e0 : p == 1 ? e1 : p == 2 ? e2 : e3) * inv;

    const float2 off = *(const float2*)&g_off[(size_t)mh * 8 + p * 2];
    const float px = (float)(q & 63) * (64.0f / 63.0f) + off.x - 0.5f;
    const float py = (float)(q >> 6) * (64.0f / 63.0f) + off.y - 0.5f;
    const float fx = floorf(px), fy = floorf(py);
    const float wx = px - fx, wy = py - fy;
    const int ix = (int)fx, iy = (int)fy;

    float wxl = (ix >= 0  && ix < 64) ? (1.f - wx) : 0.f;
    float wxr = (ix >= -1 && ix < 63) ? wx         : 0.f;
    if (ix < 0) { wxl = wxr; wxr = 0.f; }
    float wyt = (iy >= 0  && iy < 64) ? (1.f - wy) : 0.f;
    float wyb = (iy >= -1 && iy < 63) ? wy         : 0.f;
    if (iy < 0) { wyt = wyb; wyb = 0.f; }
    wyt *= awp;
    wyb *= awp;

    const int ix0 = min(max(ix, 0), 63);
    const int iy0 = min(max(iy, 0), 63);

    g_sw[t]   = make_float4(wxl * wyt, wxr * wyt, wxl * wyb, wxr * wyb);
    g_sidx[t] = (iy0 << 11) + (ix0 << 5);
}

// ---------------------------------------------------------------------------
// Gather: warp = 2 heads of one query; lane = (head, point, channel-group).
// Pure gather+FMA; all setup precomputed. Corner offsets +0,+32,+2048,+2080
// always dereference valid memory (weights zero when logically OOB).
// ---------------------------------------------------------------------------
__global__ __launch_bounds__(256) void sample_gather() {
    const int wid  = blockIdx.x * 8 + (threadIdx.x >> 5);  // 0 .. M_TOT*4-1
    const int lane = threadIdx.x & 31;
    const int m    = wid >> 2;
    const int h    = ((wid & 3) << 1) + (lane >> 4);       // 0..7
    const int p    = (lane >> 2) & 3;
    const int cg   = lane & 3;
    const int mh   = (m << 3) + h;
    const int slab = ((m >> 12) << 3) + h;                 // b*8+h

    const int t = (mh << 2) + p;
    const float4 w = __ldg(&g_sw[t]);
    const int base = __ldg(&g_sidx[t]);

    const __nv_bfloat16* __restrict__ vp =
        g_val + (size_t)slab * (NQ * HD) + base + (cg << 3);

    float acc[8];
    #pragma unroll
    for (int j = 0; j < 8; j++) acc[j] = 0.f;

    #pragma unroll
    for (int cn = 0; cn < 4; cn++) {
        const int  o  = (cn == 0 ? 0 : cn == 1 ? 32 : cn == 2 ? 2048 : 2080);
        const float cw = (cn == 0 ? w.x : cn == 1 ? w.y : cn == 2 ? w.z : w.w);
        uint4 r = *(const uint4*)(vp + o);
        const __nv_bfloat162* h2 = (const __nv_bfloat162*)&r;
        #pragma unroll
        for (int j = 0; j < 4; j++) {
            float2 f = __bfloat1622float2(h2[j]);
            acc[2*j]   = fmaf(cw, f.x, acc[2*j]);
            acc[2*j+1] = fmaf(cw, f.y, acc[2*j+1]);
        }
    }

    // reduce over the 4 points (lane bits 2,3)
    #pragma unroll
    for (int msk = 4; msk <= 8; msk <<= 1)
        #pragma unroll
        for (int j = 0; j < 8; j++)
            acc[j] += __shfl_xor_sync(0xFFFFFFFF, acc[j], msk);

    if (p == 0) {
        __nv_bfloat16 tt[8];
        #pragma unroll
        for (int j = 0; j < 8; j++) tt[j] = __float2bfloat16(acc[j]);
        *(uint4*)&g_samp[(size_t)m * E + h * HD + (cg << 3)] = *(uint4*)tt;
    }
}

// ---------------------------------------------------------------------------
extern "C" void kernel_launch(void* const* d_in, const int* in_sizes, int n_in,
                              void* d_out, int out_size) {
    const float* query   = (const float*)d_in[0];
    const float* value_w = (const float*)d_in[1];
    const float* value_b = (const float*)d_in[2];
    const float* off_w   = (const float*)d_in[3];
    const float* off_b   = (const float*)d_in[4];
    const float* attn_w  = (const float*)d_in[5];
    const float* attn_b  = (const float*)d_in[6];
    const float* out_w   = (const float*)d_in[7];
    const float* out_b   = (const float*)d_in[8];
    float* out = (float*)d_out;

    static bool attr_done = false;
    if (!attr_done) {
        cudaFuncSetAttribute(gemm1_tc, cudaFuncAttributeMaxDynamicSharedMemorySize, DYN_SMEM);
        cudaFuncSetAttribute(gemm2_tc, cudaFuncAttributeMaxDynamicSharedMemorySize, DYN_SMEM);
        attr_done = true;
    }

    prep_w<<<352, 256>>>(value_w, value_b, off_w, off_b, attn_w, attn_b, out_w);

    dim3 g1(M_TOT / BM, (N1 + BN - 1) / BN);   // 256 x 3
    gemm1_tc<<<g1, 256, DYN_SMEM>>>(query);

    sample_setup<<<(M_TOT * NH * NP) / 256, 256>>>();
    sample_gather<<<(M_TOT * 4) / 8, 256>>>();

    dim3 g2(M_TOT / BM, E / BN);               // 256 x 2
    gemm2_tc<<<g2, 256, DYN_SMEM>>>(out_b, query, out);
}

// round 17
// speedup vs baseline: 1.0982x; 1.0982x over previous
#include <cuda_runtime.h>
#include <cuda_bf16.h>
#include <mma.h>
#include <math.h>

using namespace nvcuda;

// Problem constants
#define BS   8
#define NQ   4096
#define E    256
#define NH   8
#define NP   4
#define HD   32
#define HH   64
#define WW   64
#define M_TOT (BS*NQ)      // 32768
#define N1   352

// GEMM tiling
#define BM   128
#define BN   128
#define BK   32
#define LDAH 40                    // bf16 leading dim (80B rows)
#define LDC  136                   // float C staging leading dim
#define NKT  (E/BK)                // 8
#define STAGE ((BM+BN)*LDAH)       // 10240 bf16 per stage
#define DYN_SMEM 69632             // max(2*STAGE*2 = 40960, BM*LDC*4 = 69632)

// Scratch
__device__ __nv_bfloat16 g_qb  [M_TOT*E];             // query bf16
__device__ __nv_bfloat16 g_val [BS*NH*NQ*HD + 4096];  // [b,h,pos,d] + guard pad
__device__ __nv_bfloat16 g_samp[M_TOT*E];
__device__ __nv_bfloat16 g_w1  [N1*E];
__device__ __nv_bfloat16 g_w2  [E*E];
__device__ float         g_b1  [N1];
__device__ float4        g_sw  [M_TOT*NH*NP];         // premult corner weights
__device__ int           g_sidx[M_TOT*NH*NP];         // clamped base index

// ---------------------------------------------------------------------------
__device__ __forceinline__ void cp_async16(void* sdst, const void* gsrc) {
    unsigned s = (unsigned)__cvta_generic_to_shared(sdst);
    asm volatile("cp.async.cg.shared.global [%0], [%1], 16;\n" :: "r"(s), "l"(gsrc));
}

// ---------------------------------------------------------------------------
// Prep (fused): blocks [0,4096) convert query fp32->bf16; blocks [4096,4448)
// convert/concat weights and biases.
// ---------------------------------------------------------------------------
__global__ __launch_bounds__(256) void prep_all(
        const float* __restrict__ qsrc,
        const float* __restrict__ vw, const float* __restrict__ vb,
        const float* __restrict__ ow, const float* __restrict__ ob,
        const float* __restrict__ aw, const float* __restrict__ ab,
        const float* __restrict__ outw) {
    if (blockIdx.x < 4096) {
        int i = (blockIdx.x * 256 + threadIdx.x) * 8;
        float4 u = *(const float4*)&qsrc[i];
        float4 v = *(const float4*)&qsrc[i + 4];
        __nv_bfloat16 t[8] = {
            __float2bfloat16(u.x), __float2bfloat16(u.y),
            __float2bfloat16(u.z), __float2bfloat16(u.w),
            __float2bfloat16(v.x), __float2bfloat16(v.y),
            __float2bfloat16(v.z), __float2bfloat16(v.w)};
        *(uint4*)&g_qb[i] = *(uint4*)t;
    } else {
        int i = (blockIdx.x - 4096) * 256 + threadIdx.x;
        if (i < 256*256)      g_w1[i] = __float2bfloat16(vw[i]);
        else if (i < 320*256) g_w1[i] = __float2bfloat16(ow[i - 256*256]);
        else if (i < 352*256) g_w1[i] = __float2bfloat16(aw[i - 320*256]);
        if (i < 256*256)      g_w2[i] = __float2bfloat16(outw[i]);
        if (i < 256)          g_b1[i] = vb[i];
        else if (i < 320)     g_b1[i] = ob[i - 256];
        else if (i < 352)     g_b1[i] = ab[i - 320];
    }
}

// ---------------------------------------------------------------------------
// bf16 cp.async pipelined mainloop (round-10 verified): C staged to smem fp32.
// ---------------------------------------------------------------------------
__device__ __forceinline__ void bf16_mainloop(
    const __nv_bfloat16* __restrict__ A, const __nv_bfloat16* __restrict__ B,
    int b_rows, int m0, int n0, unsigned char* smem_raw)
{
    __nv_bfloat16* buf = (__nv_bfloat16*)smem_raw;
    const int tid  = threadIdx.x;
    const int warp = tid >> 5;
    const int wr   = warp >> 2;    // 0..1 -> 64-row block
    const int wc   = warp & 3;     // 0..3 -> 32-col block

    wmma::fragment<wmma::accumulator, 16, 16, 16, float> c[4][2];
    #pragma unroll
    for (int i = 0; i < 4; i++)
        #pragma unroll
        for (int j = 0; j < 2; j++) wmma::fill_fragment(c[i][j], 0.0f);

    auto issue = [&](int s, int k0) {
        __nv_bfloat16* St = buf + s * STAGE;
        #pragma unroll
        for (int it = 0; it < 4; it++) {
            int idx = tid + it * 256;
            int row = idx >> 2, cg = idx & 3;
            const __nv_bfloat16* src;
            if (row < BM) {
                src = A + (size_t)(m0 + row) * E + k0 + cg * 8;
            } else {
                int gn = n0 + row - BM;
                if (gn >= b_rows) gn = b_rows - 1;
                src = B + (size_t)gn * E + k0 + cg * 8;
            }
            cp_async16(St + row * LDAH + cg * 8, src);
        }
        asm volatile("cp.async.commit_group;\n" ::);
    };

    auto compute = [&](int s) {
        __nv_bfloat16* As = buf + s * STAGE;
        __nv_bfloat16* Bs = As + BM * LDAH;
        #pragma unroll
        for (int kk = 0; kk < BK; kk += 16) {
            wmma::fragment<wmma::matrix_a, 16, 16, 16, __nv_bfloat16, wmma::row_major> a[4];
            wmma::fragment<wmma::matrix_b, 16, 16, 16, __nv_bfloat16, wmma::col_major> b[2];
            #pragma unroll
            for (int i = 0; i < 4; i++)
                wmma::load_matrix_sync(a[i], &As[(wr * 64 + i * 16) * LDAH + kk], LDAH);
            #pragma unroll
            for (int j = 0; j < 2; j++)
                wmma::load_matrix_sync(b[j], &Bs[(wc * 32 + j * 16) * LDAH + kk], LDAH);
            #pragma unroll
            for (int i = 0; i < 4; i++)
                #pragma unroll
                for (int j = 0; j < 2; j++)
                    wmma::mma_sync(c[i][j], a[i], b[j], c[i][j]);
        }
    };

    issue(0, 0);
    for (int kt = 0; kt < NKT; kt++) {
        if (kt + 1 < NKT) {
            issue((kt + 1) & 1, (kt + 1) * BK);
            asm volatile("cp.async.wait_group 1;\n" ::);
        } else {
            asm volatile("cp.async.wait_group 0;\n" ::);
        }
        __syncthreads();
        compute(kt & 1);
        __syncthreads();
    }

    float* Cs = (float*)smem_raw;
    #pragma unroll
    for (int i = 0; i < 4; i++)
        #pragma unroll
        for (int j = 0; j < 2; j++)
            wmma::store_matrix_sync(&Cs[(wr * 64 + i * 16) * LDC + wc * 32 + j * 16],
                                    c[i][j], LDC, wmma::mem_row_major);
    __syncthreads();
}

// ---------------------------------------------------------------------------
// GEMM1: g_qb @ g_w1^T (+bias).
//   by 0,1 : value columns -> g_val (bf16 scatter)
//   by 2   : off+attn columns -> FUSED sample setup (writes g_sw/g_sidx
//            directly from Cs; no global off/attn round-trip)
// ---------------------------------------------------------------------------
__global__ __launch_bounds__(256) void gemm1_tc() {
    extern __shared__ unsigned char smem_raw[];
    const int m0 = blockIdx.x * BM;
    const int n0 = blockIdx.y * BN;
    const int tid = threadIdx.x;

    bf16_mainloop(g_qb, g_w1, N1, m0, n0, smem_raw);
    float* Cs = (float*)smem_raw;

    if (n0 < 256) {
        // value scatter (columns all < 256 here)
        #pragma unroll
        for (int it = 0; it < 16; it++) {
            int idx = tid + it * 256;
            int mm = idx >> 5, n4 = idx & 31;
            int c = n0 + n4 * 4;
            int m = m0 + mm;
            int b = m >> 12, q = m & 4095;
            float4 v = *(float4*)&Cs[mm * LDC + n4 * 4];
            v.x += g_b1[c];     v.y += g_b1[c + 1];
            v.z += g_b1[c + 2]; v.w += g_b1[c + 3];
            int h = c >> 5, d = c & 31;
            __nv_bfloat16 t[4] = {__float2bfloat16(v.x), __float2bfloat16(v.y),
                                  __float2bfloat16(v.z), __float2bfloat16(v.w)};
            *(uint2*)&g_val[((((size_t)b << 3) + h) * NQ + q) * HD + d] = *(uint2*)t;
        }
    } else {
        // fused setup: 128 queries x 8 heads x 4 points = 4096 items
        #pragma unroll
        for (int it = 0; it < 16; it++) {
            int idx = tid + it * 256;          // 0..4095
            int mm = idx >> 5;                 // local query row
            int hp = idx & 31;
            int h = hp >> 2, p = hp & 3;
            int m = m0 + mm;
            int q = m & 4095;
            const float* Crow = &Cs[mm * LDC];

            // attn logits (Cs cols 64 + h*4 + k, bias 320 + h*4 + k)
            float a0 = Crow[64 + h * 4 + 0] + g_b1[320 + h * 4 + 0];
            float a1 = Crow[64 + h * 4 + 1] + g_b1[320 + h * 4 + 1];
            float a2 = Crow[64 + h * 4 + 2] + g_b1[320 + h * 4 + 2];
            float a3 = Crow[64 + h * 4 + 3] + g_b1[320 + h * 4 + 3];
            float mx = fmaxf(fmaxf(a0, a1), fmaxf(a2, a3));
            float e0 = __expf(a0 - mx), e1 = __expf(a1 - mx),
                  e2 = __expf(a2 - mx), e3 = __expf(a3 - mx);
            float inv = 1.f / (e0 + e1 + e2 + e3);
            float awp = (p == 0 ? e0 : p == 1 ? e1 : p == 2 ? e2 : e3) * inv;

            // offsets (Cs cols h*8 + p*2, bias 256 + ...)
            float ox = Crow[h * 8 + p * 2]     + g_b1[256 + h * 8 + p * 2];
            float oy = Crow[h * 8 + p * 2 + 1] + g_b1[256 + h * 8 + p * 2 + 1];

            const float px = (float)(q & 63) * (64.0f / 63.0f) + ox - 0.5f;
            const float py = (float)(q >> 6) * (64.0f / 63.0f) + oy - 0.5f;
            const float fx = floorf(px), fy = floorf(py);
            const float wx = px - fx, wy = py - fy;
            const int ix = (int)fx, iy = (int)fy;

            float wxl = (ix >= 0  && ix < 64) ? (1.f - wx) : 0.f;
            float wxr = (ix >= -1 && ix < 63) ? wx         : 0.f;
            if (ix < 0) { wxl = wxr; wxr = 0.f; }
            float wyt = (iy >= 0  && iy < 64) ? (1.f - wy) : 0.f;
            float wyb = (iy >= -1 && iy < 63) ? wy         : 0.f;
            if (iy < 0) { wyt = wyb; wyb = 0.f; }
            wyt *= awp;
            wyb *= awp;

            const int ix0 = min(max(ix, 0), 63);
            const int iy0 = min(max(iy, 0), 63);

            int t = (((m << 3) + h) << 2) + p;
            g_sw[t]   = make_float4(wxl * wyt, wxr * wyt, wxl * wyb, wxr * wyb);
            g_sidx[t] = (iy0 << 11) + (ix0 << 5);
        }
    }
}

// ---------------------------------------------------------------------------
// GEMM2: g_samp @ g_w2^T + out_b + 2*query -> out
// ---------------------------------------------------------------------------
__global__ __launch_bounds__(256) void gemm2_tc(const float* __restrict__ bias,
                                                const float* __restrict__ query,
                                                float* __restrict__ out) {
    extern __shared__ unsigned char smem_raw[];
    const int m0 = blockIdx.x * BM;
    const int n0 = blockIdx.y * BN;
    const int tid = threadIdx.x;

    bf16_mainloop(g_samp, g_w2, E, m0, n0, smem_raw);
    float* Cs = (float*)smem_raw;

    #pragma unroll
    for (int it = 0; it < 16; it++) {
        int idx = tid + it * 256;
        int mm = idx >> 5, n4 = idx & 31;
        int c = n0 + n4 * 4;
        size_t go = (size_t)(m0 + mm) * E + c;
        float4 v = *(float4*)&Cs[mm * LDC + n4 * 4];
        float4 bi = *(const float4*)&bias[c];
        float4 qv = *(const float4*)&query[go];
        v.x += bi.x + 2.0f * qv.x;
        v.y += bi.y + 2.0f * qv.y;
        v.z += bi.z + 2.0f * qv.z;
        v.w += bi.w + 2.0f * qv.w;
        *(float4*)&out[go] = v;
    }
}

// ---------------------------------------------------------------------------
// Gather (round-10 verified): warp = 2 heads of one query.
// ---------------------------------------------------------------------------
__global__ __launch_bounds__(256) void sample_gather() {
    const int wid  = blockIdx.x * 8 + (threadIdx.x >> 5);
    const int lane = threadIdx.x & 31;
    const int m    = wid >> 2;
    const int h    = ((wid & 3) << 1) + (lane >> 4);
    const int p    = (lane >> 2) & 3;
    const int cg   = lane & 3;
    const int mh   = (m << 3) + h;
    const int slab = ((m >> 12) << 3) + h;

    const int t = (mh << 2) + p;
    const float4 w = __ldg(&g_sw[t]);
    const int base = __ldg(&g_sidx[t]);

    const __nv_bfloat16* __restrict__ vp =
        g_val + (size_t)slab * (NQ * HD) + base + (cg << 3);

    float acc[8];
    #pragma unroll
    for (int j = 0; j < 8; j++) acc[j] = 0.f;

    #pragma unroll
    for (int cn = 0; cn < 4; cn++) {
        const int  o  = (cn == 0 ? 0 : cn == 1 ? 32 : cn == 2 ? 2048 : 2080);
        const float cw = (cn == 0 ? w.x : cn == 1 ? w.y : cn == 2 ? w.z : w.w);
        uint4 r = *(const uint4*)(vp + o);
        const __nv_bfloat162* h2 = (const __nv_bfloat162*)&r;
        #pragma unroll
        for (int j = 0; j < 4; j++) {
            float2 f = __bfloat1622float2(h2[j]);
            acc[2*j]   = fmaf(cw, f.x, acc[2*j]);
            acc[2*j+1] = fmaf(cw, f.y, acc[2*j+1]);
        }
    }

    #pragma unroll
    for (int msk = 4; msk <= 8; msk <<= 1)
        #pragma unroll
        for (int j = 0; j < 8; j++)
            acc[j] += __shfl_xor_sync(0xFFFFFFFF, acc[j], msk);

    if (p == 0) {
        __nv_bfloat16 tt[8];
        #pragma unroll
        for (int j = 0; j < 8; j++) tt[j] = __float2bfloat16(acc[j]);
        *(uint4*)&g_samp[(size_t)m * E + h * HD + (cg << 3)] = *(uint4*)tt;
    }
}

// ---------------------------------------------------------------------------
extern "C" void kernel_launch(void* const* d_in, const int* in_sizes, int n_in,
                              void* d_out, int out_size) {
    const float* query   = (const float*)d_in[0];
    const float* value_w = (const float*)d_in[1];
    const float* value_b = (const float*)d_in[2];
    const float* off_w   = (const float*)d_in[3];
    const float* off_b   = (const float*)d_in[4];
    const float* attn_w  = (const float*)d_in[5];
    const float* attn_b  = (const float*)d_in[6];
    const float* out_w   = (const float*)d_in[7];
    const float* out_b   = (const float*)d_in[8];
    float* out = (float*)d_out;

    static bool attr_done = false;
    if (!attr_done) {
        cudaFuncSetAttribute(gemm1_tc, cudaFuncAttributeMaxDynamicSharedMemorySize, DYN_SMEM);
        cudaFuncSetAttribute(gemm2_tc, cudaFuncAttributeMaxDynamicSharedMemorySize, DYN_SMEM);
        attr_done = true;
    }

    prep_all<<<4096 + 352, 256>>>(query, value_w, value_b, off_w, off_b,
                                  attn_w, attn_b, out_w);

    dim3 g1(M_TOT / BM, 3);                    // by 0,1: value; by 2: off+attn+setup
    gemm1_tc<<<g1, 256, DYN_SMEM>>>();

    sample_gather<<<(M_TOT * 4) / 8, 256>>>();

    dim3 g2(M_TOT / BM, E / BN);               // 256 x 2
    gemm2_tc<<<g2, 256, DYN_SMEM>>>(out_b, query, out);
}